// round 10
// baseline (speedup 1.0000x reference)
#include <cuda_runtime.h>
#include <cuda_bf16.h>
#include <cstdint>

// Problem constants (fixed by reference)
#define N_NODES 50000
#define R_REL   32
#define DDIM    128
#define E_EDGES 600000
#define T_TRIP  8192

#define BLK     64                         // edge rows per MMA tile
#define ROOT_TILES ((N_NODES + BLK - 1) / BLK)        // 782
#define MAX_TILES (E_EDGES / BLK + R_REL + ROOT_TILES + 2)
#define EDGE_GRID 296                      // 2 CTAs / SM
#define NB      586                        // convert/scatter blocks (1024 thr each)

// fused-prep block ranges (256 threads each)
#define XN (N_NODES * DDIM)
#define NBX (XN / 1024)                    // 6250 splitx blocks (float4 x 256)
#define NBW ((R_REL + 1) * 16)             // 528 splitw blocks
#define NBH (N_NODES * DDIM / 4 / 256)     // 6250 hinit blocks

// dynamic smem layout for edge kernel (96 KB)
#define SM_B_HI 0
#define SM_B_LO 32768
#define SM_A    65536                      // A hi at +0 (16KB), lo at +16384
#define SMEM_EDGE_BYTES 98304

__device__ __forceinline__ uint32_t smem_to_u32(const void* smem_ptr) {
    uint32_t addr;
    asm("{ .reg .u64 tmp; cvta.to.shared.u64 tmp, %1; cvt.u32.u64 %0, tmp; }"
        : "=r"(addr) : "l"(smem_ptr));
    return addr;
}
// XOR swizzle: row-major [rows][128] bf16, 256B/row, 16 chunks of 16B per row.
__device__ __forceinline__ uint32_t swz(uint32_t row, uint32_t chunk) {
    return row * 256u + ((chunk ^ (row & 7u)) << 4);
}
#define LDMX4(r, addr) \
    asm volatile("ldmatrix.sync.aligned.m8n8.x4.shared.b16 {%0,%1,%2,%3}, [%4];" \
        : "=r"((r)[0]), "=r"((r)[1]), "=r"((r)[2]), "=r"((r)[3]) : "r"(addr))
#define MMA_BF16(d, a, b0, b1) \
    asm volatile("mma.sync.aligned.m16n8k16.row.col.f32.bf16.bf16.f32 " \
        "{%0,%1,%2,%3}, {%4,%5,%6,%7}, {%8,%9}, {%0,%1,%2,%3};" \
        : "+f"((d)[0]), "+f"((d)[1]), "+f"((d)[2]), "+f"((d)[3]) \
        : "r"((a)[0]), "r"((a)[1]), "r"((a)[2]), "r"((a)[3]), "r"(b0), "r"(b1))
#define CP_ASYNC16(dst_u32, gptr) \
    asm volatile("cp.async.cg.shared.global [%0], [%1], 16;" \
        :: "r"(dst_u32), "l"(gptr) : "memory")
#define CP_COMMIT() asm volatile("cp.async.commit_group;" ::: "memory")
#define CP_WAIT0()  asm volatile("cp.async.wait_group 0;" ::: "memory")
#define REDV2(ptr, a0, a1) \
    asm volatile("red.global.add.v2.f32 [%0], {%1, %2};" \
                 :: "l"(ptr), "f"(a0), "f"(a1) : "memory")

// -------- device scratch (static, no allocation) --------
// g_cnt invariant: zero at process start (static init) and re-zeroed by
// edge_mma_kernel every pass (runs after scatter, the last reader).
__device__ int   g_cnt[N_NODES * R_REL];
__device__ float g_h[(size_t)N_NODES * DDIM];
__device__ int   g_src[E_EDGES];
__device__ int   g_tgt[E_EDGES];
__device__ int   g_rel[E_EDGES];
__device__ int   g_src_s[E_EDGES];      // relation-sorted
__device__ int   g_tgt_s[E_EDGES];
__device__ float g_norm_s[E_EDGES];
__device__ int   g_head[T_TRIP], g_tail[T_TRIP], g_ridx[T_TRIP];
__device__ int   g_bh[NB * R_REL];
__device__ int   g_boff[NB * R_REL];
__device__ int   g_off[R_REL + 1];
__device__ int   g_tile_rel[MAX_TILES];
__device__ int   g_tile_start[MAX_TILES];
__device__ int   g_ntiles;
// bf16 hi/lo splits: 33 relations (slot 32 = W_root)
__device__ __align__(16) __nv_bfloat16 g_x_hi[(size_t)N_NODES * DDIM];
__device__ __align__(16) __nv_bfloat16 g_x_lo[(size_t)N_NODES * DDIM];
__device__ __align__(16) __nv_bfloat16 g_wt_hi[(size_t)(R_REL + 1) * DDIM * DDIM];
__device__ __align__(16) __nv_bfloat16 g_wt_lo[(size_t)(R_REL + 1) * DDIM * DDIM];

__device__ __forceinline__ int ld_idx(const void* p, long long i, int is64) {
    return is64 ? (int)((const long long*)p)[i] : ((const int*)p)[i];
}

// -------- K0: convert edges+triplets, counts, fused block hist --------
__global__ void convert_kernel(const void* edge_index, const void* edge_type,
                               const void* head, const void* tail, const void* ridx) {
    __shared__ int cnt[R_REL];
    __shared__ int s_is64;
    int tid = threadIdx.x;
    if (tid < R_REL) cnt[tid] = 0;
    if (tid < 32) {
        const unsigned int* p = (const unsigned int*)edge_index;
        unsigned int v = p[2 * tid + 1] | p[2 * (tid + 32) + 1];
        unsigned int nz = __ballot_sync(0xffffffffu, v != 0u);
        if (tid == 0) s_is64 = (nz == 0u);
    }
    __syncthreads();
    int is64 = s_is64;
    long long i = (long long)blockIdx.x * 1024 + tid;
    if (i < T_TRIP) {
        g_head[i] = ld_idx(head, i, is64);
        g_tail[i] = ld_idx(tail, i, is64);
        g_ridx[i] = ld_idx(ridx, i, is64);
    }
    if (i < E_EDGES) {
        int s = ld_idx(edge_index, i, is64);
        int t = ld_idx(edge_index, (long long)E_EDGES + i, is64);
        int r = ld_idx(edge_type, i, is64);
        g_src[i] = s; g_tgt[i] = t; g_rel[i] = r;
        atomicAdd(&g_cnt[t * R_REL + r], 1);
        atomicAdd(&cnt[r], 1);
    }
    __syncthreads();
    if (tid < R_REL) g_bh[blockIdx.x * R_REL + tid] = cnt[tid];
}

// -------- K1 parts --------
__device__ void scan_body() {
    __shared__ int relTot[R_REL];
    __shared__ int relOff[R_REL + 1];
    __shared__ int tileOff[R_REL + 1];
    __shared__ int ntE_s;
    int tid = threadIdx.x, w = tid >> 5, lane = tid & 31;   // 8 warps

    for (int rr = w; rr < R_REL; rr += 8) {
        int sum = 0;
        for (int b = lane; b < NB; b += 32) sum += g_bh[b * R_REL + rr];
        #pragma unroll
        for (int o = 16; o; o >>= 1) sum += __shfl_down_sync(0xffffffffu, sum, o);
        if (lane == 0) relTot[rr] = sum;
    }
    __syncthreads();

    if (tid == 0) {
        int acc = 0, tacc = 0;
        for (int r = 0; r < R_REL; ++r) {
            relOff[r] = acc; tileOff[r] = tacc;
            acc += relTot[r];
            tacc += (relTot[r] + BLK - 1) / BLK;
        }
        relOff[R_REL] = acc; tileOff[R_REL] = tacc;
        ntE_s = tacc;
        g_ntiles = tacc + ROOT_TILES;
    }
    __syncthreads();
    if (tid <= R_REL) g_off[tid] = relOff[tid];

    for (int rr = w; rr < R_REL; rr += 8) {
        int carry = relOff[rr];
        for (int c0 = 0; c0 < NB; c0 += 32) {
            int b = c0 + lane;
            int v = (b < NB) ? g_bh[b * R_REL + rr] : 0;
            int inc = v;
            #pragma unroll
            for (int o = 1; o < 32; o <<= 1) {
                int t = __shfl_up_sync(0xffffffffu, inc, o);
                if (lane >= o) inc += t;
            }
            if (b < NB) g_boff[b * R_REL + rr] = carry + inc - v;
            carry += __shfl_sync(0xffffffffu, inc, 31);
        }
        int nt = (relTot[rr] + BLK - 1) / BLK;
        int tb = tileOff[rr], base = relOff[rr];
        for (int i = lane; i < nt; i += 32) {
            g_tile_rel[tb + i] = rr;
            g_tile_start[tb + i] = base + i * BLK;
        }
    }
    __syncthreads();
    int ntE = ntE_s;
    for (int i = tid; i < ROOT_TILES; i += 256) {
        g_tile_rel[ntE + i] = R_REL;
        g_tile_start[ntE + i] = i * BLK;
    }
}

__device__ void splitx_body(int b, const float* __restrict__ x) {
    int i = b * 256 + threadIdx.x;
    float4 v = ((const float4*)x)[i];
    __nv_bfloat16 h0 = __float2bfloat16(v.x), h1 = __float2bfloat16(v.y);
    __nv_bfloat16 h2 = __float2bfloat16(v.z), h3 = __float2bfloat16(v.w);
    __nv_bfloat162* ph = (__nv_bfloat162*)g_x_hi;
    __nv_bfloat162* pl = (__nv_bfloat162*)g_x_lo;
    ph[2 * i]     = __nv_bfloat162(h0, h1);
    ph[2 * i + 1] = __nv_bfloat162(h2, h3);
    pl[2 * i]     = __nv_bfloat162(
        __float2bfloat16(v.x - __bfloat162float(h0)),
        __float2bfloat16(v.y - __bfloat162float(h1)));
    pl[2 * i + 1] = __nv_bfloat162(
        __float2bfloat16(v.z - __bfloat162float(h2)),
        __float2bfloat16(v.w - __bfloat162float(h3)));
}

__device__ void splitw_body(int b, const float* __restrict__ W, const float* __restrict__ Wroot) {
    __shared__ __nv_bfloat16 sh[32][34];
    __shared__ __nv_bfloat16 sl[32][34];
    int r    = b >> 4;
    int tile = b & 15;
    int k0 = (tile >> 2) * 32, o0 = (tile & 3) * 32;
    int tx = threadIdx.x & 31, ty = threadIdx.x >> 5;
    const float* Wr = (r < R_REL) ? (W + ((size_t)r << 14)) : Wroot;

    #pragma unroll
    for (int ii = 0; ii < 4; ++ii) {
        int kl = ty + ii * 8;
        float v = Wr[(size_t)(k0 + kl) * DDIM + o0 + tx];
        __nv_bfloat16 hi = __float2bfloat16(v);
        sh[kl][tx] = hi;
        sl[kl][tx] = __float2bfloat16(v - __bfloat162float(hi));
    }
    __syncthreads();
    #pragma unroll
    for (int ii = 0; ii < 4; ++ii) {
        int ol = ty + ii * 8;
        size_t dst = ((size_t)r << 14) + (size_t)(o0 + ol) * DDIM + k0 + tx;
        g_wt_hi[dst] = sh[tx][ol];
        g_wt_lo[dst] = sl[tx][ol];
    }
}

__device__ void hinit_body(int b, const float* __restrict__ bias) {
    int i = b * 256 + threadIdx.x;
    const float4* b4 = (const float4*)bias;
    ((float4*)g_h)[i] = b4[i & 31];
}

// -------- K1: fused scan + splitx + splitw + hinit --------
__global__ void fused_prep_kernel(const float* __restrict__ x, const float* __restrict__ W,
                                  const float* __restrict__ Wroot, const float* __restrict__ bias) {
    int b = blockIdx.x;
    if (b == 0) { scan_body(); return; }
    b -= 1;
    if (b < NBX) { splitx_body(b, x); return; }
    b -= NBX;
    if (b < NBW) { splitw_body(b, W, Wroot); return; }
    b -= NBW;
    hinit_body(b, bias);
}

// -------- K2: scatter via smem-rank + precomputed block offsets --------
__global__ void scatter_kernel() {
    __shared__ int rank[R_REL];
    __shared__ int base[R_REL];
    int tid = threadIdx.x;
    if (tid < R_REL) {
        rank[tid] = 0;
        base[tid] = g_boff[blockIdx.x * R_REL + tid];
    }
    __syncthreads();
    int e = blockIdx.x * 1024 + tid;
    if (e >= E_EDGES) return;
    int r = g_rel[e];
    int k = atomicAdd(&rank[r], 1);
    int pos = base[r] + k;
    int t = g_tgt[e];
    g_src_s[pos] = g_src[e];
    g_tgt_s[pos] = t;
    g_norm_s[pos] = 1.0f / (float)g_cnt[t * R_REL + r];
}

// -------- K3: persistent HMMA bf16x3 GEMM, direct quad-coalesced red.v2 epilogue --------
__global__ void __launch_bounds__(256, 2)
edge_mma_kernel() {
    extern __shared__ char smem[];

    // re-zero g_cnt for the next pass
    {
        int4 z = make_int4(0, 0, 0, 0);
        int4* p = (int4*)g_cnt;
        for (int i = blockIdx.x * 256 + threadIdx.x; i < N_NODES * R_REL / 4; i += EDGE_GRID * 256)
            p[i] = z;
    }

    int ntiles = g_ntiles;
    int bid = blockIdx.x;
    int t0 = (int)(((long long)bid * ntiles) / EDGE_GRID);
    int t1 = (int)(((long long)(bid + 1) * ntiles) / EDGE_GRID);
    if (t0 >= t1) return;

    int tid  = threadIdx.x;
    int wid  = tid >> 5;
    int lane = tid & 31;
    uint32_t sbase = smem_to_u32(smem);
    int arow = tid >> 2;        // 0..63 (A gather row)
    int aq   = tid & 3;

    // warp layout: g = wid&1 (M half), nq = wid>>1 (32-col group)
    int g  = wid & 1, nq = wid >> 1;
    int m0 = g * 32, n0 = nq * 32;
    uint32_t lr = (uint32_t)(lane & 15);
    uint32_t lc = (uint32_t)(lane >> 4);
    int rl = lane >> 2;                  // row within 8-row band
    int cb = (lane & 3) * 2;             // col pair base within 8-col block

    // ---- prologue: prefetch tile t0 ----
    {
        int r = g_tile_rel[t0], start = g_tile_start[t0];
        int lim = (r == R_REL) ? N_NODES : g_off[r + 1];
        int cnt = min(BLK, lim - start);
        int nd = 0;
        if (arow < cnt) nd = (r == R_REL) ? (start + arow) : g_src_s[start + arow];
        const __nv_bfloat16* ah = g_x_hi + (size_t)nd * DDIM + aq * 32;
        const __nv_bfloat16* al = g_x_lo + (size_t)nd * DDIM + aq * 32;
        #pragma unroll
        for (int i = 0; i < 4; ++i) {
            uint32_t off = swz((uint32_t)arow, (uint32_t)(aq * 4 + i));
            CP_ASYNC16(sbase + SM_A + off, ah + i * 8);
            CP_ASYNC16(sbase + SM_A + 16384u + off, al + i * 8);
        }
        CP_COMMIT();
    }

    int prev_rel = -1;

    for (int t = t0; t < t1; ++t) {
        int r = g_tile_rel[t];
        int start = g_tile_start[t];
        bool isRoot = (r == R_REL);
        int lim = isRoot ? N_NODES : g_off[r + 1];

        CP_WAIT0();

        // ---- preload this thread's epilogue metadata (rows m0+rl+{0,8,16,24}) ----
        float wn0, wn1, wn2, wn3;
        int   tg0, tg1, tg2, tg3;
        {
            int e0 = start + m0 + rl;
            int e1 = e0 + 8, e2 = e0 + 16, e3 = e0 + 24;
            wn0 = (e0 < lim) ? (isRoot ? 1.0f : g_norm_s[e0]) : 0.0f;
            wn1 = (e1 < lim) ? (isRoot ? 1.0f : g_norm_s[e1]) : 0.0f;
            wn2 = (e2 < lim) ? (isRoot ? 1.0f : g_norm_s[e2]) : 0.0f;
            wn3 = (e3 < lim) ? (isRoot ? 1.0f : g_norm_s[e3]) : 0.0f;
            tg0 = (e0 < lim) ? (isRoot ? e0 : g_tgt_s[e0]) : -1;
            tg1 = (e1 < lim) ? (isRoot ? e1 : g_tgt_s[e1]) : -1;
            tg2 = (e2 < lim) ? (isRoot ? e2 : g_tgt_s[e2]) : -1;
            tg3 = (e3 < lim) ? (isRoot ? e3 : g_tgt_s[e3]) : -1;
        }

        if (r != prev_rel) {
            int brow = tid >> 1, bhalf = tid & 1;
            const uint4* bhp = (const uint4*)(g_wt_hi + (size_t)r * DDIM * DDIM + brow * DDIM + bhalf * 64);
            const uint4* blp = (const uint4*)(g_wt_lo + (size_t)r * DDIM * DDIM + brow * DDIM + bhalf * 64);
            #pragma unroll
            for (int i = 0; i < 8; ++i) {
                uint32_t off = swz((uint32_t)brow, (uint32_t)(bhalf * 8 + i));
                *(uint4*)(smem + SM_B_HI + off) = bhp[i];
                *(uint4*)(smem + SM_B_LO + off) = blp[i];
            }
            prev_rel = r;
        }
        __syncthreads();   // A + B visible

        // ---- MMA mainloop: D = A_hi*B_hi + A_hi*B_lo + A_lo*B_hi ----
        float acc[2][4][4];
        #pragma unroll
        for (int i = 0; i < 2; ++i)
            #pragma unroll
            for (int j = 0; j < 4; ++j)
                #pragma unroll
                for (int k = 0; k < 4; ++k) acc[i][j][k] = 0.0f;

        #pragma unroll
        for (int ks = 0; ks < 8; ++ks) {
            uint32_t chunk = (uint32_t)(ks * 2) + lc;
            uint32_t ah[2][4], al[2][4], bh[2][4], bl[2][4];
            #pragma unroll
            for (int mt = 0; mt < 2; ++mt) {
                uint32_t aoff = swz((uint32_t)(m0 + mt * 16) + lr, chunk);
                LDMX4(ah[mt], sbase + SM_A + aoff);
                LDMX4(al[mt], sbase + SM_A + 16384u + aoff);
            }
            #pragma unroll
            for (int np = 0; np < 2; ++np) {
                uint32_t boff = swz((uint32_t)(n0 + np * 16) + lr, chunk);
                LDMX4(bh[np], sbase + SM_B_HI + boff);
                LDMX4(bl[np], sbase + SM_B_LO + boff);
            }
            #pragma unroll
            for (int mt = 0; mt < 2; ++mt)
                #pragma unroll
                for (int ntl = 0; ntl < 4; ++ntl) {
                    int np = ntl >> 1, sel = ntl & 1;
                    MMA_BF16(acc[mt][ntl], ah[mt], bh[np][sel], bh[np][sel + 2]);
                }
            #pragma unroll
            for (int mt = 0; mt < 2; ++mt)
                #pragma unroll
                for (int ntl = 0; ntl < 4; ++ntl) {
                    int np = ntl >> 1, sel = ntl & 1;
                    MMA_BF16(acc[mt][ntl], ah[mt], bl[np][sel], bl[np][sel + 2]);
                }
            #pragma unroll
            for (int mt = 0; mt < 2; ++mt)
                #pragma unroll
                for (int ntl = 0; ntl < 4; ++ntl) {
                    int np = ntl >> 1, sel = ntl & 1;
                    MMA_BF16(acc[mt][ntl], al[mt], bh[np][sel], bh[np][sel + 2]);
                }
        }
        __syncthreads();   // all warps done reading A

        // ---- prefetch A for tile t+1 (overlaps epilogue REDs) ----
        if (t + 1 < t1) {
            int rn = g_tile_rel[t + 1], startn = g_tile_start[t + 1];
            int limn = (rn == R_REL) ? N_NODES : g_off[rn + 1];
            int cntn = min(BLK, limn - startn);
            int nd = 0;
            if (arow < cntn) nd = (rn == R_REL) ? (startn + arow) : g_src_s[startn + arow];
            const __nv_bfloat16* ahp = g_x_hi + (size_t)nd * DDIM + aq * 32;
            const __nv_bfloat16* alp = g_x_lo + (size_t)nd * DDIM + aq * 32;
            #pragma unroll
            for (int i = 0; i < 4; ++i) {
                uint32_t off = swz((uint32_t)arow, (uint32_t)(aq * 4 + i));
                CP_ASYNC16(sbase + SM_A + off, ahp + i * 8);
                CP_ASYNC16(sbase + SM_A + 16384u + off, alp + i * 8);
            }
            CP_COMMIT();
        }

        // ---- direct epilogue: quad-coalesced red.v2, no barriers ----
        {
            float* h0 = g_h + (size_t)(tg0 < 0 ? 0 : tg0) * DDIM + n0 + cb;
            float* h1 = g_h + (size_t)(tg1 < 0 ? 0 : tg1) * DDIM + n0 + cb;
            float* h2 = g_h + (size_t)(tg2 < 0 ? 0 : tg2) * DDIM + n0 + cb;
            float* h3 = g_h + (size_t)(tg3 < 0 ? 0 : tg3) * DDIM + n0 + cb;
            #pragma unroll
            for (int ntl = 0; ntl < 4; ++ntl) {
                int co = ntl * 8;
                if (tg0 >= 0) REDV2(h0 + co, acc[0][ntl][0] * wn0, acc[0][ntl][1] * wn0);
                if (tg1 >= 0) REDV2(h1 + co, acc[0][ntl][2] * wn1, acc[0][ntl][3] * wn1);
                if (tg2 >= 0) REDV2(h2 + co, acc[1][ntl][0] * wn2, acc[1][ntl][1] * wn2);
                if (tg3 >= 0) REDV2(h3 + co, acc[1][ntl][2] * wn3, acc[1][ntl][3] * wn3);
            }
        }
        // loop-top __syncthreads (next iteration) protects A/B buffer reuse
    }
}

// -------- K4: fused relu + DistMult scoring --------
__global__ void score_kernel(const float* __restrict__ rel_emb, float* __restrict__ out) {
    int gt = blockIdx.x * blockDim.x + threadIdx.x;
    int tri = gt >> 5;
    int lane = gt & 31;
    if (tri >= T_TRIP) return;
    int hn = g_head[tri], tn = g_tail[tri], r = g_ridx[tri];
    const float4 a = *(const float4*)&g_h[(size_t)hn * DDIM + lane * 4];
    const float4 b = *(const float4*)&g_h[(size_t)tn * DDIM + lane * 4];
    const float4 c = *(const float4*)&rel_emb[(size_t)r * DDIM + lane * 4];
    float s = fmaxf(a.x, 0.0f) * c.x * fmaxf(b.x, 0.0f)
            + fmaxf(a.y, 0.0f) * c.y * fmaxf(b.y, 0.0f)
            + fmaxf(a.z, 0.0f) * c.z * fmaxf(b.z, 0.0f)
            + fmaxf(a.w, 0.0f) * c.w * fmaxf(b.w, 0.0f);
    #pragma unroll
    for (int o = 16; o > 0; o >>= 1) s += __shfl_down_sync(0xffffffffu, s, o);
    if (lane == 0) out[tri] = s;
}

// -------- launch (edge_mma stays at launch index 3 for ncu capture) --------
extern "C" void kernel_launch(void* const* d_in, const int* in_sizes, int n_in,
                              void* d_out, int out_size) {
    const float* x        = (const float*)d_in[0];
    const float* W        = (const float*)d_in[1];
    const float* Wroot    = (const float*)d_in[2];
    const float* bias     = (const float*)d_in[3];
    const float* rel_emb  = (const float*)d_in[4];
    const void*  edge_idx = d_in[5];
    const void*  edge_typ = d_in[6];
    const void*  head     = d_in[7];
    const void*  tail     = d_in[8];
    const void*  ridx     = d_in[9];
    float* out = (float*)d_out;

    cudaFuncSetAttribute(edge_mma_kernel, cudaFuncAttributeMaxDynamicSharedMemorySize, SMEM_EDGE_BYTES);

    convert_kernel<<<NB, 1024>>>(edge_idx, edge_typ, head, tail, ridx);
    fused_prep_kernel<<<1 + NBX + NBW + NBH, 256>>>(x, W, Wroot, bias);
    scatter_kernel<<<NB, 1024>>>();
    edge_mma_kernel<<<EDGE_GRID, 256, SMEM_EDGE_BYTES>>>();
    score_kernel<<<(T_TRIP * 32 + 255) / 256, 256>>>(rel_emb, out);
}

// round 11
// speedup vs baseline: 1.5006x; 1.5006x over previous
#include <cuda_runtime.h>
#include <cuda_bf16.h>
#include <cuda_fp16.h>
#include <cstdint>

// Problem constants (fixed by reference)
#define N_NODES 50000
#define R_REL   32
#define DDIM    128
#define E_EDGES 600000
#define T_TRIP  8192

#define BLK     64                         // edge rows per MMA tile
#define ROOT_TILES ((N_NODES + BLK - 1) / BLK)        // 782
#define MAX_TILES (E_EDGES / BLK + R_REL + ROOT_TILES + 2)
#define EDGE_GRID 296                      // 2 CTAs / SM
#define NB      586                        // convert/scatter blocks (1024 thr each)

// fused-prep block ranges (256 threads each)
#define XN (N_NODES * DDIM)
#define NBX (XN / 1024)                    // 6250 splitx blocks (float4 x 256)
#define NBW ((R_REL + 1) * 16)             // 528 splitw blocks
#define NBH (N_NODES * DDIM / 4 / 256)     // 6250 hinit blocks

// dynamic smem layout for edge kernel (fp16: A is hi-only, 16 KB)
#define SM_B_HI 0
#define SM_B_LO 32768
#define SM_A    65536                      // A hi (fp16) 16 KB
#define SM_STAGE 81920                     // fp32 stage [16][132]
#define SMEM_EDGE_BYTES (81920 + 16 * 132 * 4)   // 90368

__device__ __forceinline__ uint32_t smem_to_u32(const void* smem_ptr) {
    uint32_t addr;
    asm("{ .reg .u64 tmp; cvta.to.shared.u64 tmp, %1; cvt.u32.u64 %0, tmp; }"
        : "=r"(addr) : "l"(smem_ptr));
    return addr;
}
// XOR swizzle: row-major [rows][128] f16, 256B/row, 16 chunks of 16B per row.
__device__ __forceinline__ uint32_t swz(uint32_t row, uint32_t chunk) {
    return row * 256u + ((chunk ^ (row & 7u)) << 4);
}
#define LDMX4(r, addr) \
    asm volatile("ldmatrix.sync.aligned.m8n8.x4.shared.b16 {%0,%1,%2,%3}, [%4];" \
        : "=r"((r)[0]), "=r"((r)[1]), "=r"((r)[2]), "=r"((r)[3]) : "r"(addr))
#define MMA_F16(d, a, b0, b1) \
    asm volatile("mma.sync.aligned.m16n8k16.row.col.f32.f16.f16.f32 " \
        "{%0,%1,%2,%3}, {%4,%5,%6,%7}, {%8,%9}, {%0,%1,%2,%3};" \
        : "+f"((d)[0]), "+f"((d)[1]), "+f"((d)[2]), "+f"((d)[3]) \
        : "r"((a)[0]), "r"((a)[1]), "r"((a)[2]), "r"((a)[3]), "r"(b0), "r"(b1))
#define CP_ASYNC16(dst_u32, gptr) \
    asm volatile("cp.async.cg.shared.global [%0], [%1], 16;" \
        :: "r"(dst_u32), "l"(gptr) : "memory")
#define CP_COMMIT() asm volatile("cp.async.commit_group;" ::: "memory")
#define CP_WAIT0()  asm volatile("cp.async.wait_group 0;" ::: "memory")
#define REDV4(ptr, v) \
    asm volatile("red.global.add.v4.f32 [%0], {%1, %2, %3, %4};" \
                 :: "l"(ptr), "f"((v).x), "f"((v).y), "f"((v).z), "f"((v).w) : "memory")

// -------- device scratch (static, no allocation) --------
// g_cnt invariant: zero at process start (static init) and re-zeroed by
// edge_mma_kernel every pass (runs after scatter, the last reader).
__device__ int   g_cnt[N_NODES * R_REL];
__device__ float g_h[(size_t)N_NODES * DDIM];
__device__ int   g_src[E_EDGES];
__device__ int   g_tgt[E_EDGES];
__device__ int   g_rel[E_EDGES];
__device__ int   g_src_s[E_EDGES];      // relation-sorted
__device__ int   g_tgt_s[E_EDGES];
__device__ float g_norm_s[E_EDGES];
__device__ int   g_head[T_TRIP], g_tail[T_TRIP], g_ridx[T_TRIP];
__device__ int   g_bh[NB * R_REL];
__device__ int   g_boff[NB * R_REL];
__device__ int   g_off[R_REL + 1];
__device__ int   g_tile_rel[MAX_TILES];
__device__ int   g_tile_start[MAX_TILES];
__device__ int   g_ntiles;
// fp16 operands: x single-precision-hi only; W hi+lo (33 relations, slot 32 = W_root)
__device__ __align__(16) __half g_x_h[(size_t)N_NODES * DDIM];
__device__ __align__(16) __half g_wt_hi[(size_t)(R_REL + 1) * DDIM * DDIM];
__device__ __align__(16) __half g_wt_lo[(size_t)(R_REL + 1) * DDIM * DDIM];

__device__ __forceinline__ int ld_idx(const void* p, long long i, int is64) {
    return is64 ? (int)((const long long*)p)[i] : ((const int*)p)[i];
}

// -------- K0: convert edges+triplets, counts, fused block hist --------
__global__ void convert_kernel(const void* edge_index, const void* edge_type,
                               const void* head, const void* tail, const void* ridx) {
    __shared__ int cnt[R_REL];
    __shared__ int s_is64;
    int tid = threadIdx.x;
    if (tid < R_REL) cnt[tid] = 0;
    if (tid < 32) {
        const unsigned int* p = (const unsigned int*)edge_index;
        unsigned int v = p[2 * tid + 1] | p[2 * (tid + 32) + 1];
        unsigned int nz = __ballot_sync(0xffffffffu, v != 0u);
        if (tid == 0) s_is64 = (nz == 0u);
    }
    __syncthreads();
    int is64 = s_is64;
    long long i = (long long)blockIdx.x * 1024 + tid;
    if (i < T_TRIP) {
        g_head[i] = ld_idx(head, i, is64);
        g_tail[i] = ld_idx(tail, i, is64);
        g_ridx[i] = ld_idx(ridx, i, is64);
    }
    if (i < E_EDGES) {
        int s = ld_idx(edge_index, i, is64);
        int t = ld_idx(edge_index, (long long)E_EDGES + i, is64);
        int r = ld_idx(edge_type, i, is64);
        g_src[i] = s; g_tgt[i] = t; g_rel[i] = r;
        atomicAdd(&g_cnt[t * R_REL + r], 1);
        atomicAdd(&cnt[r], 1);
    }
    __syncthreads();
    if (tid < R_REL) g_bh[blockIdx.x * R_REL + tid] = cnt[tid];
}

// -------- K1 parts --------
__device__ void scan_body() {
    __shared__ int relTot[R_REL];
    __shared__ int relOff[R_REL + 1];
    __shared__ int tileOff[R_REL + 1];
    __shared__ int ntE_s;
    int tid = threadIdx.x, w = tid >> 5, lane = tid & 31;   // 8 warps

    for (int rr = w; rr < R_REL; rr += 8) {
        int sum = 0;
        for (int b = lane; b < NB; b += 32) sum += g_bh[b * R_REL + rr];
        #pragma unroll
        for (int o = 16; o; o >>= 1) sum += __shfl_down_sync(0xffffffffu, sum, o);
        if (lane == 0) relTot[rr] = sum;
    }
    __syncthreads();

    if (tid == 0) {
        int acc = 0, tacc = 0;
        for (int r = 0; r < R_REL; ++r) {
            relOff[r] = acc; tileOff[r] = tacc;
            acc += relTot[r];
            tacc += (relTot[r] + BLK - 1) / BLK;
        }
        relOff[R_REL] = acc; tileOff[R_REL] = tacc;
        ntE_s = tacc;
        g_ntiles = tacc + ROOT_TILES;
    }
    __syncthreads();
    if (tid <= R_REL) g_off[tid] = relOff[tid];

    for (int rr = w; rr < R_REL; rr += 8) {
        int carry = relOff[rr];
        for (int c0 = 0; c0 < NB; c0 += 32) {
            int b = c0 + lane;
            int v = (b < NB) ? g_bh[b * R_REL + rr] : 0;
            int inc = v;
            #pragma unroll
            for (int o = 1; o < 32; o <<= 1) {
                int t = __shfl_up_sync(0xffffffffu, inc, o);
                if (lane >= o) inc += t;
            }
            if (b < NB) g_boff[b * R_REL + rr] = carry + inc - v;
            carry += __shfl_sync(0xffffffffu, inc, 31);
        }
        int nt = (relTot[rr] + BLK - 1) / BLK;
        int tb = tileOff[rr], base = relOff[rr];
        for (int i = lane; i < nt; i += 32) {
            g_tile_rel[tb + i] = rr;
            g_tile_start[tb + i] = base + i * BLK;
        }
    }
    __syncthreads();
    int ntE = ntE_s;
    for (int i = tid; i < ROOT_TILES; i += 256) {
        g_tile_rel[ntE + i] = R_REL;
        g_tile_start[ntE + i] = i * BLK;
    }
}

__device__ void splitx_body(int b, const float* __restrict__ x) {
    int i = b * 256 + threadIdx.x;          // float4 index
    float4 v = ((const float4*)x)[i];
    __half2* ph = (__half2*)g_x_h;
    ph[2 * i]     = __half2(__float2half(v.x), __float2half(v.y));
    ph[2 * i + 1] = __half2(__float2half(v.z), __float2half(v.w));
}

__device__ void splitw_body(int b, const float* __restrict__ W, const float* __restrict__ Wroot) {
    __shared__ __half sh[32][34];
    __shared__ __half sl[32][34];
    int r    = b >> 4;
    int tile = b & 15;
    int k0 = (tile >> 2) * 32, o0 = (tile & 3) * 32;
    int tx = threadIdx.x & 31, ty = threadIdx.x >> 5;
    const float* Wr = (r < R_REL) ? (W + ((size_t)r << 14)) : Wroot;

    #pragma unroll
    for (int ii = 0; ii < 4; ++ii) {
        int kl = ty + ii * 8;
        float v = Wr[(size_t)(k0 + kl) * DDIM + o0 + tx];
        __half hi = __float2half(v);
        sh[kl][tx] = hi;
        sl[kl][tx] = __float2half(v - __half2float(hi));
    }
    __syncthreads();
    #pragma unroll
    for (int ii = 0; ii < 4; ++ii) {
        int ol = ty + ii * 8;
        size_t dst = ((size_t)r << 14) + (size_t)(o0 + ol) * DDIM + k0 + tx;
        g_wt_hi[dst] = sh[tx][ol];
        g_wt_lo[dst] = sl[tx][ol];
    }
}

__device__ void hinit_body(int b, const float* __restrict__ bias) {
    int i = b * 256 + threadIdx.x;
    const float4* b4 = (const float4*)bias;
    ((float4*)g_h)[i] = b4[i & 31];
}

// -------- K1: fused scan + splitx + splitw + hinit --------
__global__ void fused_prep_kernel(const float* __restrict__ x, const float* __restrict__ W,
                                  const float* __restrict__ Wroot, const float* __restrict__ bias) {
    int b = blockIdx.x;
    if (b == 0) { scan_body(); return; }
    b -= 1;
    if (b < NBX) { splitx_body(b, x); return; }
    b -= NBX;
    if (b < NBW) { splitw_body(b, W, Wroot); return; }
    b -= NBW;
    hinit_body(b, bias);
}

// -------- K2: scatter via smem-rank + precomputed block offsets --------
__global__ void scatter_kernel() {
    __shared__ int rank[R_REL];
    __shared__ int base[R_REL];
    int tid = threadIdx.x;
    if (tid < R_REL) {
        rank[tid] = 0;
        base[tid] = g_boff[blockIdx.x * R_REL + tid];
    }
    __syncthreads();
    int e = blockIdx.x * 1024 + tid;
    if (e >= E_EDGES) return;
    int r = g_rel[e];
    int k = atomicAdd(&rank[r], 1);
    int pos = base[r] + k;
    int t = g_tgt[e];
    g_src_s[pos] = g_src[e];
    g_tgt_s[pos] = t;
    g_norm_s[pos] = 1.0f / (float)g_cnt[t * R_REL + r];
}

// -------- K3: persistent HMMA fp16x2 GEMM (edges + root), staged epilogue --------
__global__ void __launch_bounds__(256, 2)
edge_mma_kernel() {
    extern __shared__ char smem[];
    __shared__ int   s_tgt[2][BLK];
    __shared__ float s_norm[2][BLK];

    // re-zero g_cnt for the next pass
    {
        int4 z = make_int4(0, 0, 0, 0);
        int4* p = (int4*)g_cnt;
        for (int i = blockIdx.x * 256 + threadIdx.x; i < N_NODES * R_REL / 4; i += EDGE_GRID * 256)
            p[i] = z;
    }

    int ntiles = g_ntiles;
    int bid = blockIdx.x;
    int t0 = (int)(((long long)bid * ntiles) / EDGE_GRID);
    int t1 = (int)(((long long)(bid + 1) * ntiles) / EDGE_GRID);
    if (t0 >= t1) return;

    int tid  = threadIdx.x;
    int wid  = tid >> 5;
    int lane = tid & 31;
    uint32_t sbase = smem_to_u32(smem);
    float* stage = (float*)(smem + SM_STAGE);
    int arow = tid >> 2;        // 0..63 (A gather row)
    int aq   = tid & 3;

    // ---- prologue: prefetch tile t0 into buf 0 ----
    {
        int r = g_tile_rel[t0], start = g_tile_start[t0];
        int cnt = (r == R_REL) ? min(BLK, N_NODES - start)
                               : min(BLK, g_off[r + 1] - start);
        if (tid < BLK) {
            if (tid < cnt) {
                if (r == R_REL) { s_tgt[0][tid] = start + tid; s_norm[0][tid] = 1.0f; }
                else { s_tgt[0][tid] = g_tgt_s[start + tid]; s_norm[0][tid] = g_norm_s[start + tid]; }
            } else { s_tgt[0][tid] = -1; s_norm[0][tid] = 0.0f; }
        }
        int nd = 0;
        if (arow < cnt) nd = (r == R_REL) ? (start + arow) : g_src_s[start + arow];
        const __half* ah = g_x_h + (size_t)nd * DDIM + aq * 32;
        #pragma unroll
        for (int i = 0; i < 4; ++i) {
            uint32_t off = swz((uint32_t)arow, (uint32_t)(aq * 4 + i));
            CP_ASYNC16(sbase + SM_A + off, ah + i * 8);
        }
        CP_COMMIT();
    }

    int prev_rel = -1;
    // warp layout: mq = wid&1 (32 M rows), nq = wid>>1 (32 N cols)
    int mq = wid & 1, nq = wid >> 1;
    int m0 = mq * 32, n0 = nq * 32;
    uint32_t lr = (uint32_t)(lane & 15);
    uint32_t lc = (uint32_t)(lane >> 4);

    for (int t = t0; t < t1; ++t) {
        int cur = (t - t0) & 1;
        int r = g_tile_rel[t];

        CP_WAIT0();
        if (r != prev_rel) {
            int brow = tid >> 1, bhalf = tid & 1;
            const uint4* bhp = (const uint4*)(g_wt_hi + (size_t)r * DDIM * DDIM + brow * DDIM + bhalf * 64);
            const uint4* blp = (const uint4*)(g_wt_lo + (size_t)r * DDIM * DDIM + brow * DDIM + bhalf * 64);
            #pragma unroll
            for (int i = 0; i < 8; ++i) {
                uint32_t off = swz((uint32_t)brow, (uint32_t)(bhalf * 8 + i));
                *(uint4*)(smem + SM_B_HI + off) = bhp[i];
                *(uint4*)(smem + SM_B_LO + off) = blp[i];
            }
            prev_rel = r;
        }
        __syncthreads();   // A + B + meta visible

        // ---- MMA mainloop: D = A_h*B_hi + A_h*B_lo ----
        float acc[2][4][4];
        #pragma unroll
        for (int i = 0; i < 2; ++i)
            #pragma unroll
            for (int j = 0; j < 4; ++j)
                #pragma unroll
                for (int k = 0; k < 4; ++k) acc[i][j][k] = 0.0f;

        #pragma unroll
        for (int ks = 0; ks < 8; ++ks) {
            uint32_t chunk = (uint32_t)(ks * 2) + lc;
            uint32_t ah[2][4], bh[2][4], bl[2][4];
            #pragma unroll
            for (int mt = 0; mt < 2; ++mt) {
                uint32_t aoff = swz((uint32_t)(m0 + mt * 16) + lr, chunk);
                LDMX4(ah[mt], sbase + SM_A + aoff);
            }
            #pragma unroll
            for (int np = 0; np < 2; ++np) {
                uint32_t boff = swz((uint32_t)(n0 + np * 16) + lr, chunk);
                LDMX4(bh[np], sbase + SM_B_HI + boff);
                LDMX4(bl[np], sbase + SM_B_LO + boff);
            }
            // pass 1: Ah*Bh (8 independent chains)
            #pragma unroll
            for (int mt = 0; mt < 2; ++mt)
                #pragma unroll
                for (int ntl = 0; ntl < 4; ++ntl) {
                    int np = ntl >> 1, sel = ntl & 1;
                    MMA_F16(acc[mt][ntl], ah[mt], bh[np][sel], bh[np][sel + 2]);
                }
            // pass 2: Ah*Bl
            #pragma unroll
            for (int mt = 0; mt < 2; ++mt)
                #pragma unroll
                for (int ntl = 0; ntl < 4; ++ntl) {
                    int np = ntl >> 1, sel = ntl & 1;
                    MMA_F16(acc[mt][ntl], ah[mt], bl[np][sel], bl[np][sel + 2]);
                }
        }
        __syncthreads();   // all warps done reading A

        // ---- prefetch tile t+1 (overlaps epilogue) ----
        if (t + 1 < t1) {
            int nxt = cur ^ 1;
            int rn = g_tile_rel[t + 1], startn = g_tile_start[t + 1];
            int cntn = (rn == R_REL) ? min(BLK, N_NODES - startn)
                                     : min(BLK, g_off[rn + 1] - startn);
            if (tid < BLK) {
                if (tid < cntn) {
                    if (rn == R_REL) { s_tgt[nxt][tid] = startn + tid; s_norm[nxt][tid] = 1.0f; }
                    else { s_tgt[nxt][tid] = g_tgt_s[startn + tid]; s_norm[nxt][tid] = g_norm_s[startn + tid]; }
                } else { s_tgt[nxt][tid] = -1; s_norm[nxt][tid] = 0.0f; }
            }
            int nd = 0;
            if (arow < cntn) nd = (rn == R_REL) ? (startn + arow) : g_src_s[startn + arow];
            const __half* ahp = g_x_h + (size_t)nd * DDIM + aq * 32;
            #pragma unroll
            for (int i = 0; i < 4; ++i) {
                uint32_t off = swz((uint32_t)arow, (uint32_t)(aq * 4 + i));
                CP_ASYNC16(sbase + SM_A + off, ahp + i * 8);
            }
            CP_COMMIT();
        }

        // ---- staged epilogue: 4 phases of 16 rows, coalesced red.v4 ----
        #pragma unroll
        for (int p = 0; p < 4; ++p) {
            if ((wid & 1) == (p >> 1)) {
                int mt = p & 1;
                int rl = lane >> 2;
                float fl = s_norm[cur][p * 16 + rl];
                float fh = s_norm[cur][p * 16 + 8 + rl];
                #pragma unroll
                for (int ntl = 0; ntl < 4; ++ntl) {
                    int col = n0 + ntl * 8 + (lane & 3) * 2;
                    float* sp = stage + rl * 132 + col;
                    sp[0] = acc[mt][ntl][0] * fl;
                    sp[1] = acc[mt][ntl][1] * fl;
                    float* sq = stage + (rl + 8) * 132 + col;
                    sq[0] = acc[mt][ntl][2] * fh;
                    sq[1] = acc[mt][ntl][3] * fh;
                }
            }
            __syncthreads();
            {
                int row = tid >> 4;
                int f4 = tid & 15;
                int tgt = s_tgt[cur][p * 16 + row];
                if (tgt >= 0) {
                    float* hp = g_h + (size_t)tgt * DDIM;
                    const float* sp = stage + row * 132;
                    float4 v0 = *(const float4*)(sp + f4 * 4);
                    float4 v1 = *(const float4*)(sp + (f4 + 16) * 4);
                    REDV4(hp + f4 * 4, v0);
                    REDV4(hp + 64 + f4 * 4, v1);
                }
            }
            __syncthreads();
        }
    }
}

// -------- K4: fused relu + DistMult scoring --------
__global__ void score_kernel(const float* __restrict__ rel_emb, float* __restrict__ out) {
    int gt = blockIdx.x * blockDim.x + threadIdx.x;
    int tri = gt >> 5;
    int lane = gt & 31;
    if (tri >= T_TRIP) return;
    int hn = g_head[tri], tn = g_tail[tri], r = g_ridx[tri];
    const float4 a = *(const float4*)&g_h[(size_t)hn * DDIM + lane * 4];
    const float4 b = *(const float4*)&g_h[(size_t)tn * DDIM + lane * 4];
    const float4 c = *(const float4*)&rel_emb[(size_t)r * DDIM + lane * 4];
    float s = fmaxf(a.x, 0.0f) * c.x * fmaxf(b.x, 0.0f)
            + fmaxf(a.y, 0.0f) * c.y * fmaxf(b.y, 0.0f)
            + fmaxf(a.z, 0.0f) * c.z * fmaxf(b.z, 0.0f)
            + fmaxf(a.w, 0.0f) * c.w * fmaxf(b.w, 0.0f);
    #pragma unroll
    for (int o = 16; o > 0; o >>= 1) s += __shfl_down_sync(0xffffffffu, s, o);
    if (lane == 0) out[tri] = s;
}

// -------- launch (edge_mma stays at launch index 3 for ncu capture) --------
extern "C" void kernel_launch(void* const* d_in, const int* in_sizes, int n_in,
                              void* d_out, int out_size) {
    const float* x        = (const float*)d_in[0];
    const float* W        = (const float*)d_in[1];
    const float* Wroot    = (const float*)d_in[2];
    const float* bias     = (const float*)d_in[3];
    const float* rel_emb  = (const float*)d_in[4];
    const void*  edge_idx = d_in[5];
    const void*  edge_typ = d_in[6];
    const void*  head     = d_in[7];
    const void*  tail     = d_in[8];
    const void*  ridx     = d_in[9];
    float* out = (float*)d_out;

    cudaFuncSetAttribute(edge_mma_kernel, cudaFuncAttributeMaxDynamicSharedMemorySize, SMEM_EDGE_BYTES);

    convert_kernel<<<NB, 1024>>>(edge_idx, edge_typ, head, tail, ridx);
    fused_prep_kernel<<<1 + NBX + NBW + NBH, 256>>>(x, W, Wroot, bias);
    scatter_kernel<<<NB, 1024>>>();
    edge_mma_kernel<<<EDGE_GRID, 256, SMEM_EDGE_BYTES>>>();
    score_kernel<<<(T_TRIP * 32 + 255) / 256, 256>>>(rel_emb, out);
}

// round 12
// speedup vs baseline: 1.6661x; 1.1103x over previous
#include <cuda_runtime.h>
#include <cuda_bf16.h>
#include <cuda_fp16.h>
#include <cstdint>

// Problem constants (fixed by reference)
#define N_NODES 50000
#define R_REL   32
#define DDIM    128
#define E_EDGES 600000
#define T_TRIP  8192

#define BLK     64                         // edge rows per MMA tile
#define ROOT_TILES ((N_NODES + BLK - 1) / BLK)        // 782
#define MAX_TILES (E_EDGES / BLK + R_REL + ROOT_TILES + 2)
#define EDGE_GRID 296                      // 2 CTAs / SM
#define NB      586                        // convert/scatter blocks (1024 thr each)

// fused-prep block ranges (256 threads each)
#define XN (N_NODES * DDIM)
#define NBX (XN / 1024)                    // 6250 splitx blocks (float4 x 256)
#define NBW ((R_REL + 1) * 16)             // 528 splitw blocks
#define NBH (N_NODES * DDIM / 4 / 256)     // 6250 hinit blocks

// dynamic smem layout for edge kernel (fp16 single precision W)
#define SM_B    0                          // B hi (fp16) 32 KB
#define SM_A    32768                      // A (fp16) 16 KB
#define SM_STAGE 49152                     // fp32 stage [16][132]
#define SMEM_EDGE_BYTES (49152 + 16 * 132 * 4)   // 57600

__device__ __forceinline__ uint32_t smem_to_u32(const void* smem_ptr) {
    uint32_t addr;
    asm("{ .reg .u64 tmp; cvta.to.shared.u64 tmp, %1; cvt.u32.u64 %0, tmp; }"
        : "=r"(addr) : "l"(smem_ptr));
    return addr;
}
// XOR swizzle: row-major [rows][128] f16, 256B/row, 16 chunks of 16B per row.
__device__ __forceinline__ uint32_t swz(uint32_t row, uint32_t chunk) {
    return row * 256u + ((chunk ^ (row & 7u)) << 4);
}
#define LDMX4(r, addr) \
    asm volatile("ldmatrix.sync.aligned.m8n8.x4.shared.b16 {%0,%1,%2,%3}, [%4];" \
        : "=r"((r)[0]), "=r"((r)[1]), "=r"((r)[2]), "=r"((r)[3]) : "r"(addr))
#define MMA_F16(d, a, b0, b1) \
    asm volatile("mma.sync.aligned.m16n8k16.row.col.f32.f16.f16.f32 " \
        "{%0,%1,%2,%3}, {%4,%5,%6,%7}, {%8,%9}, {%0,%1,%2,%3};" \
        : "+f"((d)[0]), "+f"((d)[1]), "+f"((d)[2]), "+f"((d)[3]) \
        : "r"((a)[0]), "r"((a)[1]), "r"((a)[2]), "r"((a)[3]), "r"(b0), "r"(b1))
#define CP_ASYNC16(dst_u32, gptr) \
    asm volatile("cp.async.cg.shared.global [%0], [%1], 16;" \
        :: "r"(dst_u32), "l"(gptr) : "memory")
#define CP_COMMIT() asm volatile("cp.async.commit_group;" ::: "memory")
#define CP_WAIT0()  asm volatile("cp.async.wait_group 0;" ::: "memory")
#define REDV4(ptr, v) \
    asm volatile("red.global.add.v4.f32 [%0], {%1, %2, %3, %4};" \
                 :: "l"(ptr), "f"((v).x), "f"((v).y), "f"((v).z), "f"((v).w) : "memory")

// -------- device scratch (static, no allocation) --------
// g_cnt invariant: zero at process start (static init) and re-zeroed by
// edge_mma_kernel every pass (runs after scatter, the last reader).
__device__ int   g_cnt[N_NODES * R_REL];
__device__ float g_h[(size_t)N_NODES * DDIM];
__device__ int   g_src[E_EDGES];
__device__ int   g_tgt[E_EDGES];
__device__ int   g_rel[E_EDGES];
__device__ int   g_src_s[E_EDGES];      // relation-sorted
__device__ int   g_tgt_s[E_EDGES];
__device__ float g_norm_s[E_EDGES];
__device__ int   g_head[T_TRIP], g_tail[T_TRIP], g_ridx[T_TRIP];
__device__ int   g_bh[NB * R_REL];
__device__ int   g_boff[NB * R_REL];
__device__ int   g_off[R_REL + 1];
__device__ int   g_tile_rel[MAX_TILES];
__device__ int   g_tile_start[MAX_TILES];
__device__ int   g_ntiles;
// fp16 operands: x and W^T (33 relations, slot 32 = W_root)
__device__ __align__(16) __half g_x_h[(size_t)N_NODES * DDIM];
__device__ __align__(16) __half g_wt_h[(size_t)(R_REL + 1) * DDIM * DDIM];

__device__ __forceinline__ int ld_idx(const void* p, long long i, int is64) {
    return is64 ? (int)((const long long*)p)[i] : ((const int*)p)[i];
}

// -------- K0: convert edges+triplets, counts, fused block hist --------
__global__ void convert_kernel(const void* edge_index, const void* edge_type,
                               const void* head, const void* tail, const void* ridx) {
    __shared__ int cnt[R_REL];
    __shared__ int s_is64;
    int tid = threadIdx.x;
    if (tid < R_REL) cnt[tid] = 0;
    if (tid < 32) {
        const unsigned int* p = (const unsigned int*)edge_index;
        unsigned int v = p[2 * tid + 1] | p[2 * (tid + 32) + 1];
        unsigned int nz = __ballot_sync(0xffffffffu, v != 0u);
        if (tid == 0) s_is64 = (nz == 0u);
    }
    __syncthreads();
    int is64 = s_is64;
    long long i = (long long)blockIdx.x * 1024 + tid;
    if (i < T_TRIP) {
        g_head[i] = ld_idx(head, i, is64);
        g_tail[i] = ld_idx(tail, i, is64);
        g_ridx[i] = ld_idx(ridx, i, is64);
    }
    if (i < E_EDGES) {
        int s = ld_idx(edge_index, i, is64);
        int t = ld_idx(edge_index, (long long)E_EDGES + i, is64);
        int r = ld_idx(edge_type, i, is64);
        g_src[i] = s; g_tgt[i] = t; g_rel[i] = r;
        atomicAdd(&g_cnt[t * R_REL + r], 1);
        atomicAdd(&cnt[r], 1);
    }
    __syncthreads();
    if (tid < R_REL) g_bh[blockIdx.x * R_REL + tid] = cnt[tid];
}

// -------- K1 parts --------
__device__ void scan_body() {
    __shared__ int relTot[R_REL];
    __shared__ int relOff[R_REL + 1];
    __shared__ int tileOff[R_REL + 1];
    __shared__ int ntE_s;
    int tid = threadIdx.x, w = tid >> 5, lane = tid & 31;   // 8 warps

    for (int rr = w; rr < R_REL; rr += 8) {
        int sum = 0;
        for (int b = lane; b < NB; b += 32) sum += g_bh[b * R_REL + rr];
        #pragma unroll
        for (int o = 16; o; o >>= 1) sum += __shfl_down_sync(0xffffffffu, sum, o);
        if (lane == 0) relTot[rr] = sum;
    }
    __syncthreads();

    if (tid == 0) {
        int acc = 0, tacc = 0;
        for (int r = 0; r < R_REL; ++r) {
            relOff[r] = acc; tileOff[r] = tacc;
            acc += relTot[r];
            tacc += (relTot[r] + BLK - 1) / BLK;
        }
        relOff[R_REL] = acc; tileOff[R_REL] = tacc;
        ntE_s = tacc;
        g_ntiles = tacc + ROOT_TILES;
    }
    __syncthreads();
    if (tid <= R_REL) g_off[tid] = relOff[tid];

    for (int rr = w; rr < R_REL; rr += 8) {
        int carry = relOff[rr];
        for (int c0 = 0; c0 < NB; c0 += 32) {
            int b = c0 + lane;
            int v = (b < NB) ? g_bh[b * R_REL + rr] : 0;
            int inc = v;
            #pragma unroll
            for (int o = 1; o < 32; o <<= 1) {
                int t = __shfl_up_sync(0xffffffffu, inc, o);
                if (lane >= o) inc += t;
            }
            if (b < NB) g_boff[b * R_REL + rr] = carry + inc - v;
            carry += __shfl_sync(0xffffffffu, inc, 31);
        }
        int nt = (relTot[rr] + BLK - 1) / BLK;
        int tb = tileOff[rr], base = relOff[rr];
        for (int i = lane; i < nt; i += 32) {
            g_tile_rel[tb + i] = rr;
            g_tile_start[tb + i] = base + i * BLK;
        }
    }
    __syncthreads();
    int ntE = ntE_s;
    for (int i = tid; i < ROOT_TILES; i += 256) {
        g_tile_rel[ntE + i] = R_REL;
        g_tile_start[ntE + i] = i * BLK;
    }
}

__device__ void splitx_body(int b, const float* __restrict__ x) {
    int i = b * 256 + threadIdx.x;          // float4 index
    float4 v = ((const float4*)x)[i];
    __half2* ph = (__half2*)g_x_h;
    ph[2 * i]     = __half2(__float2half(v.x), __float2half(v.y));
    ph[2 * i + 1] = __half2(__float2half(v.z), __float2half(v.w));
}

__device__ void splitw_body(int b, const float* __restrict__ W, const float* __restrict__ Wroot) {
    __shared__ __half sh[32][34];
    int r    = b >> 4;
    int tile = b & 15;
    int k0 = (tile >> 2) * 32, o0 = (tile & 3) * 32;
    int tx = threadIdx.x & 31, ty = threadIdx.x >> 5;
    const float* Wr = (r < R_REL) ? (W + ((size_t)r << 14)) : Wroot;

    #pragma unroll
    for (int ii = 0; ii < 4; ++ii) {
        int kl = ty + ii * 8;
        float v = Wr[(size_t)(k0 + kl) * DDIM + o0 + tx];
        sh[kl][tx] = __float2half(v);
    }
    __syncthreads();
    #pragma unroll
    for (int ii = 0; ii < 4; ++ii) {
        int ol = ty + ii * 8;
        size_t dst = ((size_t)r << 14) + (size_t)(o0 + ol) * DDIM + k0 + tx;
        g_wt_h[dst] = sh[tx][ol];
    }
}

__device__ void hinit_body(int b, const float* __restrict__ bias) {
    int i = b * 256 + threadIdx.x;
    const float4* b4 = (const float4*)bias;
    ((float4*)g_h)[i] = b4[i & 31];
}

// -------- K1: fused scan + splitx + splitw + hinit --------
__global__ void fused_prep_kernel(const float* __restrict__ x, const float* __restrict__ W,
                                  const float* __restrict__ Wroot, const float* __restrict__ bias) {
    int b = blockIdx.x;
    if (b == 0) { scan_body(); return; }
    b -= 1;
    if (b < NBX) { splitx_body(b, x); return; }
    b -= NBX;
    if (b < NBW) { splitw_body(b, W, Wroot); return; }
    b -= NBW;
    hinit_body(b, bias);
}

// -------- K2: scatter via smem-rank + precomputed block offsets --------
__global__ void scatter_kernel() {
    __shared__ int rank[R_REL];
    __shared__ int base[R_REL];
    int tid = threadIdx.x;
    if (tid < R_REL) {
        rank[tid] = 0;
        base[tid] = g_boff[blockIdx.x * R_REL + tid];
    }
    __syncthreads();
    int e = blockIdx.x * 1024 + tid;
    if (e >= E_EDGES) return;
    int r = g_rel[e];
    int k = atomicAdd(&rank[r], 1);
    int pos = base[r] + k;
    int t = g_tgt[e];
    g_src_s[pos] = g_src[e];
    g_tgt_s[pos] = t;
    g_norm_s[pos] = 1.0f / (float)g_cnt[t * R_REL + r];
}

// -------- K3: persistent HMMA fp16 single-pass GEMM, staged red.v4 epilogue --------
__global__ void __launch_bounds__(256, 2)
edge_mma_kernel() {
    extern __shared__ char smem[];
    __shared__ int   s_tgt[2][BLK];
    __shared__ float s_norm[2][BLK];

    // re-zero g_cnt for the next pass
    {
        int4 z = make_int4(0, 0, 0, 0);
        int4* p = (int4*)g_cnt;
        for (int i = blockIdx.x * 256 + threadIdx.x; i < N_NODES * R_REL / 4; i += EDGE_GRID * 256)
            p[i] = z;
    }

    int ntiles = g_ntiles;
    int bid = blockIdx.x;
    int t0 = (int)(((long long)bid * ntiles) / EDGE_GRID);
    int t1 = (int)(((long long)(bid + 1) * ntiles) / EDGE_GRID);
    if (t0 >= t1) return;

    int tid  = threadIdx.x;
    int wid  = tid >> 5;
    int lane = tid & 31;
    uint32_t sbase = smem_to_u32(smem);
    float* stage = (float*)(smem + SM_STAGE);
    int arow = tid >> 2;        // 0..63 (A gather row)
    int aq   = tid & 3;

    // ---- prologue: prefetch tile t0 into buf 0 ----
    {
        int r = g_tile_rel[t0], start = g_tile_start[t0];
        int cnt = (r == R_REL) ? min(BLK, N_NODES - start)
                               : min(BLK, g_off[r + 1] - start);
        if (tid < BLK) {
            if (tid < cnt) {
                if (r == R_REL) { s_tgt[0][tid] = start + tid; s_norm[0][tid] = 1.0f; }
                else { s_tgt[0][tid] = g_tgt_s[start + tid]; s_norm[0][tid] = g_norm_s[start + tid]; }
            } else { s_tgt[0][tid] = -1; s_norm[0][tid] = 0.0f; }
        }
        int nd = 0;
        if (arow < cnt) nd = (r == R_REL) ? (start + arow) : g_src_s[start + arow];
        const __half* ah = g_x_h + (size_t)nd * DDIM + aq * 32;
        #pragma unroll
        for (int i = 0; i < 4; ++i) {
            uint32_t off = swz((uint32_t)arow, (uint32_t)(aq * 4 + i));
            CP_ASYNC16(sbase + SM_A + off, ah + i * 8);
        }
        CP_COMMIT();
    }

    int prev_rel = -1;
    // warp layout: mq = wid&1 (32 M rows), nq = wid>>1 (32 N cols)
    int mq = wid & 1, nq = wid >> 1;
    int m0 = mq * 32, n0 = nq * 32;
    uint32_t lr = (uint32_t)(lane & 15);
    uint32_t lc = (uint32_t)(lane >> 4);

    for (int t = t0; t < t1; ++t) {
        int cur = (t - t0) & 1;
        int r = g_tile_rel[t];

        CP_WAIT0();
        if (r != prev_rel) {
            int brow = tid >> 1, bhalf = tid & 1;
            const uint4* bhp = (const uint4*)(g_wt_h + (size_t)r * DDIM * DDIM + brow * DDIM + bhalf * 64);
            #pragma unroll
            for (int i = 0; i < 8; ++i) {
                uint32_t off = swz((uint32_t)brow, (uint32_t)(bhalf * 8 + i));
                *(uint4*)(smem + SM_B + off) = bhp[i];
            }
            prev_rel = r;
        }
        __syncthreads();   // A + B + meta visible

        // ---- MMA mainloop: single fp16 pass ----
        float acc[2][4][4];
        #pragma unroll
        for (int i = 0; i < 2; ++i)
            #pragma unroll
            for (int j = 0; j < 4; ++j)
                #pragma unroll
                for (int k = 0; k < 4; ++k) acc[i][j][k] = 0.0f;

        #pragma unroll
        for (int ks = 0; ks < 8; ++ks) {
            uint32_t chunk = (uint32_t)(ks * 2) + lc;
            uint32_t ah[2][4], bh[2][4];
            #pragma unroll
            for (int mt = 0; mt < 2; ++mt) {
                uint32_t aoff = swz((uint32_t)(m0 + mt * 16) + lr, chunk);
                LDMX4(ah[mt], sbase + SM_A + aoff);
            }
            #pragma unroll
            for (int np = 0; np < 2; ++np) {
                uint32_t boff = swz((uint32_t)(n0 + np * 16) + lr, chunk);
                LDMX4(bh[np], sbase + SM_B + boff);
            }
            #pragma unroll
            for (int mt = 0; mt < 2; ++mt)
                #pragma unroll
                for (int ntl = 0; ntl < 4; ++ntl) {
                    int np = ntl >> 1, sel = ntl & 1;
                    MMA_F16(acc[mt][ntl], ah[mt], bh[np][sel], bh[np][sel + 2]);
                }
        }
        __syncthreads();   // all warps done reading A

        // ---- prefetch tile t+1 (overlaps epilogue) ----
        if (t + 1 < t1) {
            int nxt = cur ^ 1;
            int rn = g_tile_rel[t + 1], startn = g_tile_start[t + 1];
            int cntn = (rn == R_REL) ? min(BLK, N_NODES - startn)
                                     : min(BLK, g_off[rn + 1] - startn);
            if (tid < BLK) {
                if (tid < cntn) {
                    if (rn == R_REL) { s_tgt[nxt][tid] = startn + tid; s_norm[nxt][tid] = 1.0f; }
                    else { s_tgt[nxt][tid] = g_tgt_s[startn + tid]; s_norm[nxt][tid] = g_norm_s[startn + tid]; }
                } else { s_tgt[nxt][tid] = -1; s_norm[nxt][tid] = 0.0f; }
            }
            int nd = 0;
            if (arow < cntn) nd = (rn == R_REL) ? (startn + arow) : g_src_s[startn + arow];
            const __half* ahp = g_x_h + (size_t)nd * DDIM + aq * 32;
            #pragma unroll
            for (int i = 0; i < 4; ++i) {
                uint32_t off = swz((uint32_t)arow, (uint32_t)(aq * 4 + i));
                CP_ASYNC16(sbase + SM_A + off, ahp + i * 8);
            }
            CP_COMMIT();
        }

        // ---- staged epilogue: 4 phases of 16 rows, coalesced red.v4 ----
        #pragma unroll
        for (int p = 0; p < 4; ++p) {
            if ((wid & 1) == (p >> 1)) {
                int mt = p & 1;
                int rl = lane >> 2;
                float fl = s_norm[cur][p * 16 + rl];
                float fh = s_norm[cur][p * 16 + 8 + rl];
                #pragma unroll
                for (int ntl = 0; ntl < 4; ++ntl) {
                    int col = n0 + ntl * 8 + (lane & 3) * 2;
                    float* sp = stage + rl * 132 + col;
                    sp[0] = acc[mt][ntl][0] * fl;
                    sp[1] = acc[mt][ntl][1] * fl;
                    float* sq = stage + (rl + 8) * 132 + col;
                    sq[0] = acc[mt][ntl][2] * fh;
                    sq[1] = acc[mt][ntl][3] * fh;
                }
            }
            __syncthreads();
            {
                int row = tid >> 4;
                int f4 = tid & 15;
                int tgt = s_tgt[cur][p * 16 + row];
                if (tgt >= 0) {
                    float* hp = g_h + (size_t)tgt * DDIM;
                    const float* sp = stage + row * 132;
                    float4 v0 = *(const float4*)(sp + f4 * 4);
                    float4 v1 = *(const float4*)(sp + (f4 + 16) * 4);
                    REDV4(hp + f4 * 4, v0);
                    REDV4(hp + 64 + f4 * 4, v1);
                }
            }
            __syncthreads();
        }
    }
}

// -------- K4: fused relu + DistMult scoring --------
__global__ void score_kernel(const float* __restrict__ rel_emb, float* __restrict__ out) {
    int gt = blockIdx.x * blockDim.x + threadIdx.x;
    int tri = gt >> 5;
    int lane = gt & 31;
    if (tri >= T_TRIP) return;
    int hn = g_head[tri], tn = g_tail[tri], r = g_ridx[tri];
    const float4 a = *(const float4*)&g_h[(size_t)hn * DDIM + lane * 4];
    const float4 b = *(const float4*)&g_h[(size_t)tn * DDIM + lane * 4];
    const float4 c = *(const float4*)&rel_emb[(size_t)r * DDIM + lane * 4];
    float s = fmaxf(a.x, 0.0f) * c.x * fmaxf(b.x, 0.0f)
            + fmaxf(a.y, 0.0f) * c.y * fmaxf(b.y, 0.0f)
            + fmaxf(a.z, 0.0f) * c.z * fmaxf(b.z, 0.0f)
            + fmaxf(a.w, 0.0f) * c.w * fmaxf(b.w, 0.0f);
    #pragma unroll
    for (int o = 16; o > 0; o >>= 1) s += __shfl_down_sync(0xffffffffu, s, o);
    if (lane == 0) out[tri] = s;
}

// -------- launch (edge_mma stays at launch index 3 for ncu capture) --------
extern "C" void kernel_launch(void* const* d_in, const int* in_sizes, int n_in,
                              void* d_out, int out_size) {
    const float* x        = (const float*)d_in[0];
    const float* W        = (const float*)d_in[1];
    const float* Wroot    = (const float*)d_in[2];
    const float* bias     = (const float*)d_in[3];
    const float* rel_emb  = (const float*)d_in[4];
    const void*  edge_idx = d_in[5];
    const void*  edge_typ = d_in[6];
    const void*  head     = d_in[7];
    const void*  tail     = d_in[8];
    const void*  ridx     = d_in[9];
    float* out = (float*)d_out;

    cudaFuncSetAttribute(edge_mma_kernel, cudaFuncAttributeMaxDynamicSharedMemorySize, SMEM_EDGE_BYTES);

    convert_kernel<<<NB, 1024>>>(edge_idx, edge_typ, head, tail, ridx);
    fused_prep_kernel<<<1 + NBX + NBW + NBH, 256>>>(x, W, Wroot, bias);
    scatter_kernel<<<NB, 1024>>>();
    edge_mma_kernel<<<EDGE_GRID, 256, SMEM_EDGE_BYTES>>>();
    score_kernel<<<(T_TRIP * 32 + 255) / 256, 256>>>(rel_emb, out);
}